// round 17
// baseline (speedup 1.0000x reference)
#include <cuda_runtime.h>
#include <cuda_bf16.h>

// B=32, S=12, F=128, K=8, H=64, C=64, N=512
// Math collapse: all N nodes share x[:, -1, :] -> both GAT softmaxes are
// exactly uniform and att@Wh == Wh. a1/a2 are dead inputs.
//   wh[b, k*H+h]  = sum_f x[b,11,f] * W_heads[k,f,h]   (then ELU)
//   who[b, c]     = sum_j elu_wh[b,j] * W_out[j, c]
//   out[b, c']    = sum_c who[b,c] * Wfsum[c',c] + bf[c'],
//   Wfsum[c',c]   = sum_n Wf[c', n*64 + c]
//
// Single fused kernel, 416 blocks = ONE resident wave (3 blocks/SM enforced):
//   [0,128)   P1: Wf half-row reduction -> g_part[cp][half][c]  (8.4MB DRAM)
//   [128,384) P2: elu(wh) -> g_wh                               (L2 GEMV)
//   [384,416) C : who GEMV + wfsum(2 partials) + final GEMV -> out
// Consumers have the highest bids => producers scheduled first => spins are
// deadlock-free; with one wave everyone is resident from t=0, so C starts the
// moment counters land. Counters reset by last C block (graph-replay safe).

__device__ float g_wh  [32 * 512];      // elu(wh)[b][j]
__device__ float g_part[64 * 2 * 64];   // partial Wf row-sums [cp][half][c]
__device__ int   g_c1;                  // P1 blocks done (128)
__device__ int   g_c2;                  // P2 blocks done (256)
__device__ int   g_done;                // C blocks done (32)

__device__ __forceinline__ float4 f4add(float4 a, float4 b) {
    return make_float4(a.x + b.x, a.y + b.y, a.z + b.z, a.w + b.w);
}

// shared pool (C branch is the largest user):
//   [0,2048)       hps[512]f      | P2: xs[128]f | P1: sa[256]f4 (4KB ok)
//   [2048,6144)    red[256]f4     | P2: red[256]f4
//   [6144,22784)   wfs[64*65]f (padded rows -> conflict-free final GEMV)
//   [22784,23040)  who_s[64]f
//   [23040,24064)  red2[256]f
#define POOL_BYTES 24064

__global__ __launch_bounds__(256, 3) void k_fused(
    const float* __restrict__ x,        // (32,12,128)
    const float* __restrict__ Wheads,   // (8,128,64)
    const float* __restrict__ Wout,     // (512,64)
    const float* __restrict__ Wf,       // (64, 32768)
    const float* __restrict__ bf,       // (64)
    float* __restrict__ out)            // (32,64)
{
    __shared__ __align__(16) char pool[POOL_BYTES];
    const int bid = blockIdx.x;
    const int t   = threadIdx.x;

    if (bid < 128) {
        // ------- P1: half-row reduction of Wf. 16 indep float4 loads/thread ------
        float4* sa = reinterpret_cast<float4*>(pool);
        const int cp   = bid >> 1;
        const int half = bid & 1;
        const float4* base = reinterpret_cast<const float4*>(Wf + cp * 32768 + half * 16384);

        // element c4-lane of base4[t + 256*j] is constant (= t & 15) since 256 % 16 == 0
        float4 s0 = make_float4(0.f, 0.f, 0.f, 0.f);
        float4 s1 = s0, s2 = s0, s3 = s0;
#pragma unroll
        for (int j = 0; j < 4; ++j) {
            const float4 v0 = __ldg(base + t + (4 * j + 0) * 256);
            const float4 v1 = __ldg(base + t + (4 * j + 1) * 256);
            const float4 v2 = __ldg(base + t + (4 * j + 2) * 256);
            const float4 v3 = __ldg(base + t + (4 * j + 3) * 256);
            s0 = f4add(s0, v0); s1 = f4add(s1, v1);
            s2 = f4add(s2, v2); s3 = f4add(s3, v3);
        }
        sa[t] = f4add(f4add(s0, s1), f4add(s2, s3));
        __syncthreads();

        if (t < 16) {
            float4 s = make_float4(0.f, 0.f, 0.f, 0.f);
#pragma unroll
            for (int m = 0; m < 16; ++m) s = f4add(s, sa[t + 16 * m]);
            float* dst = g_part + cp * 128 + half * 64 + 4 * t;
            dst[0] = s.x; dst[1] = s.y; dst[2] = s.z; dst[3] = s.w;
        }
        __syncthreads();
        if (t == 0) { __threadfence(); atomicAdd(&g_c1, 1); }

    } else if (bid < 384) {
        // --------------------- P2: elu(wh) -> g_wh ------------------------------
        float*  xs  = reinterpret_cast<float*>(pool);
        float4* red = reinterpret_cast<float4*>(pool + 2048);
        const int bk = bid - 128;
        const int b  = bk >> 3;
        const int k  = bk & 7;

        if (t < 128) xs[t] = x[b * (12 * 128) + 11 * 128 + t];
        __syncthreads();

        const int h4 = t & 15;
        const int fp = t >> 4;
        const float4* wb = reinterpret_cast<const float4*>(Wheads + k * (128 * 64));

        float4 acc = make_float4(0.f, 0.f, 0.f, 0.f);
#pragma unroll
        for (int i = 0; i < 8; ++i) {
            const int f = fp * 8 + i;
            const float4 w = __ldg(wb + f * 16 + h4);
            const float xv = xs[f];
            acc.x = fmaf(xv, w.x, acc.x);
            acc.y = fmaf(xv, w.y, acc.y);
            acc.z = fmaf(xv, w.z, acc.z);
            acc.w = fmaf(xv, w.w, acc.w);
        }
        red[t] = acc;
        __syncthreads();
        if (t < 128) red[t] = f4add(red[t], red[t + 128]);
        __syncthreads();
        if (t < 64)  red[t] = f4add(red[t], red[t + 64]);
        __syncthreads();
        if (t < 32)  red[t] = f4add(red[t], red[t + 32]);
        __syncthreads();
        if (t < 16) {
            float4 s = f4add(red[t], red[t + 16]);
            // ELU (alpha = 1)
            s.x = s.x > 0.f ? s.x : (expf(s.x) - 1.f);
            s.y = s.y > 0.f ? s.y : (expf(s.y) - 1.f);
            s.z = s.z > 0.f ? s.z : (expf(s.z) - 1.f);
            s.w = s.w > 0.f ? s.w : (expf(s.w) - 1.f);
            reinterpret_cast<float4*>(g_wh + b * 512 + k * 64)[t] = s;
        }
        __syncthreads();
        if (t == 0) { __threadfence(); atomicAdd(&g_c2, 1); }

    } else {
        // ------- C: who GEMV + wfsum (2 partials) + final GEMV -> out -----------
        float*  hps   = reinterpret_cast<float*>(pool);
        float4* red   = reinterpret_cast<float4*>(pool + 2048);
        float*  wfs   = reinterpret_cast<float*>(pool + 6144);   // [64][65]
        float*  who_s = reinterpret_cast<float*>(pool + 22784);
        float*  red2  = reinterpret_cast<float*>(pool + 23040);
        const int b = bid - 384;

        // gate on P2 (g_wh ready)
        if (t == 0) {
            while (atomicAdd(&g_c2, 0) < 256) __nanosleep(32);
            __threadfence();
        }
        __syncthreads();

        hps[t]       = g_wh[b * 512 + t];
        hps[t + 256] = g_wh[b * 512 + 256 + t];
        __syncthreads();

        // who partial: t = jp*16 + c4; 4 independent accumulators (chain 8)
        const int c4 = t & 15;
        const int jp = t >> 4;
        const float4* wo = reinterpret_cast<const float4*>(Wout);
        float4 a0 = make_float4(0.f, 0.f, 0.f, 0.f);
        float4 a1 = a0, a2 = a0, a3 = a0;
#pragma unroll
        for (int i = 0; i < 8; ++i) {
            const int j = jp * 32 + i;
            const float4 w0 = __ldg(wo + (j     ) * 16 + c4);
            const float4 w1 = __ldg(wo + (j +  8) * 16 + c4);
            const float4 w2 = __ldg(wo + (j + 16) * 16 + c4);
            const float4 w3 = __ldg(wo + (j + 24) * 16 + c4);
            const float h0 = hps[j], h1 = hps[j + 8], h2 = hps[j + 16], h3 = hps[j + 24];
            a0.x = fmaf(h0, w0.x, a0.x); a0.y = fmaf(h0, w0.y, a0.y);
            a0.z = fmaf(h0, w0.z, a0.z); a0.w = fmaf(h0, w0.w, a0.w);
            a1.x = fmaf(h1, w1.x, a1.x); a1.y = fmaf(h1, w1.y, a1.y);
            a1.z = fmaf(h1, w1.z, a1.z); a1.w = fmaf(h1, w1.w, a1.w);
            a2.x = fmaf(h2, w2.x, a2.x); a2.y = fmaf(h2, w2.y, a2.y);
            a2.z = fmaf(h2, w2.z, a2.z); a2.w = fmaf(h2, w2.w, a2.w);
            a3.x = fmaf(h3, w3.x, a3.x); a3.y = fmaf(h3, w3.y, a3.y);
            a3.z = fmaf(h3, w3.z, a3.z); a3.w = fmaf(h3, w3.w, a3.w);
        }
        red[t] = f4add(f4add(a0, a1), f4add(a2, a3));

        // gate on P1 (g_part ready)
        if (t == 0) {
            while (atomicAdd(&g_c1, 0) < 128) __nanosleep(32);
            __threadfence();
        }
        __syncthreads();

        // wfsum into padded smem: 4 outputs/thread, 8 independent float4 loads
        const float4* gp4 = reinterpret_cast<const float4*>(g_part); // [(cp*2+half)*16 + c4]
#pragma unroll
        for (int p = 0; p < 4; ++p) {
            const int idx = p * 256 + t;         // float4 idx into wfsum[64][16]
            const int cp  = idx >> 4;
            const int cc4 = idx & 15;
            const float4 u = __ldg(gp4 + (cp * 2    ) * 16 + cc4);
            const float4 v = __ldg(gp4 + (cp * 2 + 1) * 16 + cc4);
            float* w = wfs + cp * 65 + 4 * cc4;
            w[0] = u.x + v.x; w[1] = u.y + v.y; w[2] = u.z + v.z; w[3] = u.w + v.w;
        }
        __syncthreads();

        // reduce who partials
        if (t < 128) red[t] = f4add(red[t], red[t + 128]);
        __syncthreads();
        if (t < 64)  red[t] = f4add(red[t], red[t + 64]);
        __syncthreads();
        if (t < 32)  red[t] = f4add(red[t], red[t + 32]);
        __syncthreads();
        if (t < 16) {
            const float4 s = f4add(red[t], red[t + 16]);
            who_s[4 * t + 0] = s.x;
            who_s[4 * t + 1] = s.y;
            who_s[4 * t + 2] = s.z;
            who_s[4 * t + 3] = s.w;
        }
        __syncthreads();

        // final GEMV: t = part*64 + cp (padded wfs rows -> conflict-free)
        const int cp   = t & 63;
        const int part = t >> 6;
        float a = 0.f;
#pragma unroll
        for (int j = 0; j < 16; ++j) {
            const int c = part * 16 + j;
            a = fmaf(who_s[c], wfs[cp * 65 + c], a);
        }
        red2[t] = a;
        __syncthreads();

        if (t < 64) {
            out[b * 64 + t] = red2[t] + red2[64 + t] + red2[128 + t] + red2[192 + t]
                            + __ldg(bf + t);
        }
        __syncthreads();

        // last consumer resets counters for the next graph replay
        if (t == 0) {
            const int d = atomicAdd(&g_done, 1);
            if (d == 31) {
                atomicExch(&g_c1, 0);
                atomicExch(&g_c2, 0);
                atomicExch(&g_done, 0);
            }
        }
    }
}

// ---------------------------------------------------------------------------
extern "C" void kernel_launch(void* const* d_in, const int* in_sizes, int n_in,
                              void* d_out, int out_size)
{
    // metadata order: x, W_heads, a1_heads, a2_heads, W_out, a1_out, a2_out, Wf, bf
    const float* x      = (const float*)d_in[0];
    const float* Wheads = (const float*)d_in[1];
    const float* Wout   = (const float*)d_in[4];
    const float* Wf     = (const float*)d_in[7];
    const float* bf     = (const float*)d_in[8];
    float* out = (float*)d_out;

    k_fused<<<416, 256>>>(x, Wheads, Wout, Wf, bf, out);
}